// round 4
// baseline (speedup 1.0000x reference)
#include <cuda_runtime.h>
#include <math.h>
#include <stdint.h>

#define Bn 128
#define Tn 1024
#define Hn 512

// ---------------------------------------------------------------------------
// Phase 1: pre[t][b][:] = X[b][t][:] @ Wx + bias   (written into d_out, [T,B,H])
// ---------------------------------------------------------------------------
__global__ __launch_bounds__(256) void gemm_xw(
    const float* __restrict__ X,    // [B*T, H] rows r = b*T + t
    const float* __restrict__ Wx,   // [H, H]
    const float* __restrict__ bias, // [H]
    float* __restrict__ out)        // [T, B, H]
{
    __shared__ float As[16][132];
    __shared__ float Bs[16][68];

    const int bm0 = blockIdx.y * 128;
    const int bn0 = blockIdx.x * 64;
    const int tid = threadIdx.x;
    const int tr  = (tid >> 4) << 3;
    const int tc  = (tid & 15) << 2;

    float acc[8][4];
#pragma unroll
    for (int i = 0; i < 8; i++)
#pragma unroll
        for (int j = 0; j < 4; j++) acc[i][j] = 0.0f;

    for (int k0 = 0; k0 < Hn; k0 += 16) {
#pragma unroll
        for (int v = 0; v < 2; v++) {
            int f   = tid + (v << 8);
            int row = f >> 2;
            int kk  = (f & 3) << 2;
            float4 a = *(const float4*)(X + (size_t)(bm0 + row) * Hn + k0 + kk);
            As[kk + 0][row] = a.x;
            As[kk + 1][row] = a.y;
            As[kk + 2][row] = a.z;
            As[kk + 3][row] = a.w;
        }
        {
            int kk  = tid >> 4;
            int col = (tid & 15) << 2;
            *(float4*)&Bs[kk][col] =
                *(const float4*)(Wx + (size_t)(k0 + kk) * Hn + bn0 + col);
        }
        __syncthreads();

#pragma unroll
        for (int kk = 0; kk < 16; kk++) {
            float4 a0 = *(const float4*)&As[kk][tr];
            float4 a1 = *(const float4*)&As[kk][tr + 4];
            float4 b0 = *(const float4*)&Bs[kk][tc];
            float av[8] = {a0.x, a0.y, a0.z, a0.w, a1.x, a1.y, a1.z, a1.w};
            float bv[4] = {b0.x, b0.y, b0.z, b0.w};
#pragma unroll
            for (int i = 0; i < 8; i++)
#pragma unroll
                for (int j = 0; j < 4; j++)
                    acc[i][j] = fmaf(av[i], bv[j], acc[i][j]);
        }
        __syncthreads();
    }

    float4 bb = *(const float4*)(bias + bn0 + tc);
#pragma unroll
    for (int i = 0; i < 8; i++) {
        int m = bm0 + tr + i;
        int b = m >> 10;
        int t = m & 1023;
        float4 o;
        o.x = acc[i][0] + bb.x;
        o.y = acc[i][1] + bb.y;
        o.z = acc[i][2] + bb.z;
        o.w = acc[i][3] + bb.w;
        *(float4*)(out + ((size_t)t * Bn + b) * Hn + bn0 + tc) = o;
    }
}

// ---------------------------------------------------------------------------
// Phase 2: cluster-of-8 persistent RNN.
//  - 16 independent clusters (one per 8-row batch group); rank rk owns
//    columns [64rk, 64rk+64).
//  - Local full 8x512 state slice, double-buffered.
//  - FMA: warp = 8 rows x 16 cols, 4 outputs/thread, k split in 4 quarters
//    across warp quartets; packed fma.rn.f32x2; smem reduction across k-quarters.
//  - Exchange: stage 8x64 chunk locally, push float4s (each warp streams
//    512B to ONE peer rank). One cluster barrier per step.
// ---------------------------------------------------------------------------
#define SSTR 516                            // state row stride (floats)
#define SBUF_FLOATS (8 * SSTR)              // 4128
#define SBUF_BYTES  (SBUF_FLOATS * 4)       // 16512
#define WSTR 516                            // Whs column stride (floats)
#define WHS_FLOATS (64 * WSTR)              // 33024
#define RSTR 68                             // red/stage row stride (floats)
#define REDQ_FLOATS (8 * RSTR)              // 544 per k-quarter
#define RED_FLOATS  (4 * REDQ_FLOATS)       // 2176
#define STAGE_FLOATS REDQ_FLOATS            // 544
#define SMEM_TOTAL_FLOATS (WHS_FLOATS + 2 * SBUF_FLOATS + RED_FLOATS + STAGE_FLOATS)
#define SMEM_TOTAL_BYTES (SMEM_TOTAL_FLOATS * 4)   // 176000

__device__ __forceinline__ unsigned smem_u32(const void* p) {
    return (unsigned)__cvta_generic_to_shared(p);
}
__device__ __forceinline__ unsigned mapa_u32(unsigned addr, unsigned rank) {
    unsigned r;
    asm("mapa.shared::cluster.u32 %0, %1, %2;" : "=r"(r) : "r"(addr), "r"(rank));
    return r;
}
__device__ __forceinline__ void st_cluster_f4(unsigned addr, float4 v) {
    asm volatile("st.shared::cluster.v4.f32 [%0], {%1,%2,%3,%4};"
                 :: "r"(addr), "f"(v.x), "f"(v.y), "f"(v.z), "f"(v.w) : "memory");
}
#define CL_ARRIVE() asm volatile("barrier.cluster.arrive.aligned;" ::: "memory")
#define CL_WAIT()   asm volatile("barrier.cluster.wait.aligned;" ::: "memory")

// Packed dual-FMA: acc(f32x2) += a(f32x2) * b(f32x2), IEEE fp32 per lane.
#define FMA2(acc, a, b) \
    asm("fma.rn.f32x2 %0, %1, %2, %0;" : "+l"(acc) : "l"(a), "l"(b))

union UF2 { unsigned long long u; float2 f; };

__global__ __launch_bounds__(512, 1) __cluster_dims__(8, 1, 1)
void rnn_steps(const float* __restrict__ state0,  // [B, H]
               const float* __restrict__ Wh,      // [H, H]
               float* __restrict__ out)           // [T, B, H] (holds pre on entry)
{
    extern __shared__ float sm[];
    float* Whs   = sm;                              // [64][WSTR] Wh cols, col-major
    float* Sbuf  = sm + WHS_FLOATS;                 // [2][8][SSTR] state slice
    float* red   = Sbuf + 2 * SBUF_FLOATS;          // [4][8][RSTR] k-partials
    float* stage = red + RED_FLOATS;                // [8][RSTR] new chunk staging

    const int tid = threadIdx.x;
    unsigned rk;
    asm("mov.u32 %0, %%cluster_ctarank;" : "=r"(rk));
    const int rg = blockIdx.x >> 3;                 // row group 0..15
    const int r0 = rg * 8;
    const int c0 = (int)rk * 64;

    // ---- one-time: Wh[:, c0:c0+64] transposed into Whs[c][k] ----
#pragma unroll 4
    for (int i = 0; i < 64; i++) {
        int f = tid + i * 512;
        int k = f >> 6;
        int c = f & 63;
        Whs[c * WSTR + k] = Wh[(size_t)k * Hn + c0 + c];
    }

    // ---- one-time: FULL initial state rows [r0,r0+8) into buf 0 ----
#pragma unroll
    for (int i = 0; i < 8; i++) {
        int f = tid + i * 512;
        int r = f >> 9;
        int k = f & 511;
        Sbuf[r * SSTR + k] = state0[(size_t)(r0 + r) * Hn + k];
    }

    // ---- compute mapping: warp w -> (kq = w>>2, cb = w&3); lane -> (r, cg) ----
    const int w    = tid >> 5;
    const int lane = tid & 31;
    const int kq   = w >> 2;                  // k quarter 0..3
    const int cb   = w & 3;                   // 16-col block 0..3
    const int rr   = lane >> 2;               // row 0..7
    const int cg   = lane & 3;                // col quad 0..3
    const int C0   = cb * 16 + cg * 4;        // first of 4 local cols

    const int kbase = kq * 128;
    const float* w0p = Whs + (C0 + 0) * WSTR + kbase;
    const float* w1p = Whs + (C0 + 1) * WSTR + kbase;
    const float* w2p = Whs + (C0 + 2) * WSTR + kbase;
    const float* w3p = Whs + (C0 + 3) * WSTR + kbase;

    // ---- output mapping (one element per thread), same as exchange mapping ----
    const int r2 = lane & 7;
    const int c2 = (w << 2) + (lane >> 3);
    float* op = out + (size_t)(r0 + r2) * Hn + c0 + c2;

    // ---- push mapping: two (rank, float4) jobs per thread ----
    const int g    = tid;                     // job ids g and g+512
    const int prow = (g & 127) >> 4;          // chunk row 0..7
    const int pc4  = (g & 15) * 4;            // chunk col (float4) 0..60
    const unsigned sA = (unsigned)(g >> 7);         // rank 0..3
    const unsigned sB = sA + 4u;                    // rank 4..7
    const float* stsrc = stage + prow * RSTR + pc4;
    unsigned dstA, dstB;
    {
        unsigned own = smem_u32(Sbuf + prow * SSTR + c0 + pc4);
        dstA = mapa_u32(own, sA);
        dstB = mapa_u32(own, sB);
    }

    CL_ARRIVE();                               // init visible cluster-wide
    CL_WAIT();

    float pre = op[0];                         // prefetch pre-activation t=0

    for (int t = 0; t < Tn; t++) {
        const float* Sc = Sbuf + (t & 1) * SBUF_FLOATS + rr * SSTR + kbase;

        unsigned long long a0 = 0ull, a1 = 0ull, a2 = 0ull, a3 = 0ull;
#pragma unroll 2
        for (int k = 0; k < 128; k += 4) {
            ulonglong2 sv = *(const ulonglong2*)(Sc + k);
            ulonglong2 v0 = *(const ulonglong2*)(w0p + k);
            ulonglong2 v1 = *(const ulonglong2*)(w1p + k);
            ulonglong2 v2 = *(const ulonglong2*)(w2p + k);
            ulonglong2 v3 = *(const ulonglong2*)(w3p + k);
            FMA2(a0, sv.x, v0.x);  FMA2(a0, sv.y, v0.y);
            FMA2(a1, sv.x, v1.x);  FMA2(a1, sv.y, v1.y);
            FMA2(a2, sv.x, v2.x);  FMA2(a2, sv.y, v2.y);
            FMA2(a3, sv.x, v3.x);  FMA2(a3, sv.y, v3.y);
        }
        UF2 u0, u1, u2, u3;
        u0.u = a0; u1.u = a1; u2.u = a2; u3.u = a3;
        float4 part;
        part.x = u0.f.x + u0.f.y;
        part.y = u1.f.x + u1.f.y;
        part.z = u2.f.x + u2.f.y;
        part.w = u3.f.x + u3.f.y;
        *(float4*)(red + kq * REDQ_FLOATS + rr * RSTR + C0) = part;
        __syncthreads();

        // ---- final value for this thread's (r2, c2) ----
        const int ro = r2 * RSTR + c2;
        float s = (red[0 * REDQ_FLOATS + ro] + red[1 * REDQ_FLOATS + ro]) +
                  (red[2 * REDQ_FLOATS + ro] + red[3 * REDQ_FLOATS + ro]);
        const float v = tanhf(pre + s);

        if (t != Tn - 1) {
            stage[ro] = v;
            __syncthreads();                   // stage complete
            const unsigned noff = (unsigned)(((t + 1) & 1) * SBUF_BYTES);
            float4 pv = *(const float4*)stsrc;
            st_cluster_f4(dstA + noff, pv);    // warp-coherent 512B streams
            st_cluster_f4(dstB + noff, pv);
            CL_ARRIVE();                       // release pushes
            op[(size_t)t * (Bn * Hn)] = v;     // output (fire & forget)
            pre = op[(size_t)(t + 1) * (Bn * Hn)];  // prefetch under barrier
            CL_WAIT();                         // acquire
        } else {
            op[(size_t)t * (Bn * Hn)] = v;
        }
    }

    // Exit safety: peers may still have in-flight DSMEM stores to this CTA.
    CL_ARRIVE();
    CL_WAIT();
}

extern "C" void kernel_launch(void* const* d_in, const int* in_sizes, int n_in,
                              void* d_out, int out_size)
{
    const float* X    = (const float*)d_in[0];  // inputs_tensor [B,T,H]
    const float* S0   = (const float*)d_in[1];  // state_tensor  [1,B,H]
    const float* Wx   = (const float*)d_in[2];  // [H,H]
    const float* Wh   = (const float*)d_in[3];  // [H,H]
    const float* bias = (const float*)d_in[4];  // [H]
    float* out = (float*)d_out;                 // [T,B,H]

    (void)in_sizes; (void)n_in; (void)out_size;

    cudaFuncSetAttribute(rnn_steps,
                         cudaFuncAttributeMaxDynamicSharedMemorySize,
                         SMEM_TOTAL_BYTES);

    dim3 g1(Hn / 64, (Bn * Tn) / 128);  // (8, 1024)
    gemm_xw<<<g1, 256>>>(X, Wx, bias, out);

    rnn_steps<<<128, 512, SMEM_TOTAL_BYTES>>>(S0, Wh, out);
}

// round 6
// speedup vs baseline: 3.9846x; 3.9846x over previous
#include <cuda_runtime.h>
#include <math.h>
#include <stdint.h>

#define Bn 128
#define Tn 1024
#define Hn 512

// Packed dual-FMA: acc(f32x2) += a(f32x2) * b(f32x2), IEEE fp32 per lane.
#define FMA2(acc, a, b) \
    asm("fma.rn.f32x2 %0, %1, %2, %0;" : "+l"(acc) : "l"(a), "l"(b))
#define DUP2(d, f) \
    asm("mov.b64 %0, {%1, %1};" : "=l"(d) : "f"(f))
#define PACK2(d, lo, hi) \
    asm("mov.b64 %0, {%1, %2};" : "=l"(d) : "f"(lo), "f"(hi))

union UF2 { unsigned long long u; float2 f; };

// Per-(rowgroup, step) arrival counters. Zeroed by a graph node each launch.
__device__ unsigned g_cnt[16 * 1024];

__global__ void zero_cnt() {
    int i = blockIdx.x * blockDim.x + threadIdx.x;
    if (i < 16 * 1024) g_cnt[i] = 0u;
}

// ---------------------------------------------------------------------------
// Phase 1: pre[t][b][:] = X[b][t][:] @ Wx + bias   (into d_out, [T,B,H])
// BM=128, BN=64, BK=16, 256 threads, 8x4/thread, fma.rn.f32x2 inner loop.
// ---------------------------------------------------------------------------
__global__ __launch_bounds__(256) void gemm_xw(
    const float* __restrict__ X,    // [B*T, H] rows r = b*T + t
    const float* __restrict__ Wx,   // [H, H]
    const float* __restrict__ bias, // [H]
    float* __restrict__ out)        // [T, B, H]
{
    __shared__ float As[16][132];
    __shared__ float Bs[16][68];

    const int bm0 = blockIdx.y * 128;
    const int bn0 = blockIdx.x * 64;
    const int tid = threadIdx.x;
    const int tr  = (tid >> 4) << 3;
    const int tc  = (tid & 15) << 2;

    unsigned long long acc2[8][2];
#pragma unroll
    for (int i = 0; i < 8; i++) { acc2[i][0] = 0ull; acc2[i][1] = 0ull; }

    for (int k0 = 0; k0 < Hn; k0 += 16) {
#pragma unroll
        for (int v = 0; v < 2; v++) {
            int f   = tid + (v << 8);
            int row = f >> 2;
            int kk  = (f & 3) << 2;
            float4 a = *(const float4*)(X + (size_t)(bm0 + row) * Hn + k0 + kk);
            As[kk + 0][row] = a.x;
            As[kk + 1][row] = a.y;
            As[kk + 2][row] = a.z;
            As[kk + 3][row] = a.w;
        }
        {
            int kk  = tid >> 4;
            int col = (tid & 15) << 2;
            *(float4*)&Bs[kk][col] =
                *(const float4*)(Wx + (size_t)(k0 + kk) * Hn + bn0 + col);
        }
        __syncthreads();

#pragma unroll
        for (int kk = 0; kk < 16; kk++) {
            float4 a0 = *(const float4*)&As[kk][tr];
            float4 a1 = *(const float4*)&As[kk][tr + 4];
            ulonglong2 bv = *(const ulonglong2*)&Bs[kk][tc];
            float av[8] = {a0.x, a0.y, a0.z, a0.w, a1.x, a1.y, a1.z, a1.w};
#pragma unroll
            for (int i = 0; i < 8; i++) {
                unsigned long long d;
                DUP2(d, av[i]);
                FMA2(acc2[i][0], d, bv.x);
                FMA2(acc2[i][1], d, bv.y);
            }
        }
        __syncthreads();
    }

    float4 bb = *(const float4*)(bias + bn0 + tc);
#pragma unroll
    for (int i = 0; i < 8; i++) {
        int m = bm0 + tr + i;
        int b = m >> 10;              // T = 1024
        int t = m & 1023;
        UF2 lo, hi;
        lo.u = acc2[i][0];
        hi.u = acc2[i][1];
        float4 o;
        o.x = lo.f.x + bb.x;
        o.y = lo.f.y + bb.y;
        o.z = hi.f.x + bb.z;
        o.w = hi.f.y + bb.w;
        *(float4*)(out + ((size_t)t * Bn + b) * Hn + bn0 + tc) = o;
    }
}

// ---------------------------------------------------------------------------
// Phase 2: ONE persistent kernel. 128 CTAs = 16 rowgroups x 8 colgroups.
// CTA (rg,cg): 8 batch rows x 64 cols. Per-rowgroup sync through L2:
//   producer: stcg chunk -> fence -> atomicAdd(cnt[rg][t])
//   consumer: one thread spins until cnt[rg][t] == 8
// Wh slice lives in REGISTERS (thread: 2 cols x 32 k as 32 f32x2 regs).
// State slice staged in smem each step (ldcg from out[t-1], L2-resident).
// Warp w: k-chunk [32w, 32w+32), all 64 cols; lane -> cols {2l, 2l+1},
// rows 0..7. State LDS is warp-uniform (pure broadcast). k-split x16
// partials reduced through smem; tanh epilogue; stcg to out[t].
// ---------------------------------------------------------------------------
#define SSTR 520                          // state row stride (floats)
#define SBUF_FLOATS (8 * SSTR)            // 4160
#define PSQ 544                           // partials per k-chunk (8 x 68)
#define PS_FLOATS (16 * PSQ)              // 8704
#define RNN_SMEM_BYTES ((SBUF_FLOATS + PS_FLOATS) * 4)   // 51456

__global__ __launch_bounds__(512) void rnn_steps(
    const float* __restrict__ state0,  // [B, H]
    const float* __restrict__ Wh,      // [H, H]
    float* __restrict__ out)           // [T, B, H] (holds pre on entry)
{
    extern __shared__ float sm[];
    float* Sbuf = sm;                     // [8][SSTR] state slice
    float* Ps   = sm + SBUF_FLOATS;       // [16][8][68] k-chunk partials

    const int tid  = threadIdx.x;
    const int w    = tid >> 5;            // warp 0..15 = k-chunk
    const int lane = tid & 31;
    const int cg   = blockIdx.x & 7;
    const int rg   = blockIdx.x >> 3;
    const int c0   = cg * 64;
    const int r0   = rg * 8;

    // ---- one-time: weights into registers ----
    // w2[c][j] = (Wh[32w+2j][c0+2*lane+c], Wh[32w+2j+1][c0+2*lane+c])
    const int gc = c0 + lane * 2;
    unsigned long long w2a[16], w2b[16];
    {
        const float* wb = Wh + (size_t)(w * 32) * Hn + gc;
#pragma unroll
        for (int j = 0; j < 16; j++) {
            float a0 = wb[(2 * j) * Hn];
            float a1 = wb[(2 * j + 1) * Hn];
            float b0 = wb[(2 * j) * Hn + 1];
            float b1 = wb[(2 * j + 1) * Hn + 1];
            PACK2(w2a[j], a0, a1);
            PACK2(w2b[j], b0, b1);
        }
    }

    // epilogue mapping: one output element per thread
    const int rr = tid >> 6;              // 0..7
    const int cc = tid & 63;              // 0..63
    float* opbase = out + (size_t)(r0 + rr) * Hn + c0 + cc;

    // staging mapping: 2 float4 per thread
    const int s_r  = tid >> 7;            // 0..3 (+4 on second)
    const int s_k4 = (tid & 127) << 2;    // 0..508

    unsigned* cnt = &g_cnt[rg * 1024];

    for (int t = 0; t < Tn; t++) {
        // ---- stage state rows [r0, r0+8) from L2 (bypass L1) ----
        const float* prev = (t == 0) ? state0
                                     : (out + (size_t)(t - 1) * (Bn * Hn));
        {
            const float4* p0 =
                (const float4*)(prev + (size_t)(r0 + s_r) * Hn + s_k4);
            const float4* p1 =
                (const float4*)(prev + (size_t)(r0 + s_r + 4) * Hn + s_k4);
            float4 v0 = __ldcg(p0);
            float4 v1 = __ldcg(p1);
            *(float4*)(Sbuf + s_r * SSTR + s_k4)       = v0;
            *(float4*)(Sbuf + (s_r + 4) * SSTR + s_k4) = v1;
        }
        __syncthreads();

        float* op = opbase + (size_t)t * (Bn * Hn);
        float pre = __ldcg(op);           // own pre-activation (overlaps compute)

        // ---- compute: rows 0..7, cols {gc, gc+1}, k in [32w, 32w+32) ----
        unsigned long long acc[8][2];
#pragma unroll
        for (int r = 0; r < 8; r++) { acc[r][0] = 0ull; acc[r][1] = 0ull; }

        const float* sp = Sbuf + w * 32;
#pragma unroll
        for (int jj = 0; jj < 8; jj++) {
            const int k = jj * 4;
#pragma unroll
            for (int r = 0; r < 8; r++) {
                ulonglong2 sv = *(const ulonglong2*)(sp + r * SSTR + k);
                FMA2(acc[r][0], sv.x, w2a[2 * jj]);
                FMA2(acc[r][0], sv.y, w2a[2 * jj + 1]);
                FMA2(acc[r][1], sv.x, w2b[2 * jj]);
                FMA2(acc[r][1], sv.y, w2b[2 * jj + 1]);
            }
        }

        // ---- write partials (float2 per row, contiguous across lanes) ----
        {
            float* pb = Ps + w * PSQ + lane * 2;
#pragma unroll
            for (int r = 0; r < 8; r++) {
                UF2 u0, u1;
                u0.u = acc[r][0];
                u1.u = acc[r][1];
                float2 p;
                p.x = u0.f.x + u0.f.y;
                p.y = u1.f.x + u1.f.y;
                *(float2*)(pb + r * 68) = p;
            }
        }
        __syncthreads();

        // ---- reduce 16 k-chunks + tanh epilogue ----
        {
            const float* pp = Ps + rr * 68 + cc;
            float s = 0.0f;
#pragma unroll
            for (int q = 0; q < 16; q++) s += pp[q * PSQ];
            __stcg(op, tanhf(pre + s));
        }

        if (t != Tn - 1) {
            __syncthreads();              // all output stores issued
            if (tid == 0) {
                __threadfence();          // publish chunk before arrive
                atomicAdd(&cnt[t], 1u);
                while (*(volatile unsigned*)&cnt[t] < 8u) { }
                __threadfence();          // acquire
            }
            __syncthreads();              // release whole CTA into t+1
        }
    }
}

extern "C" void kernel_launch(void* const* d_in, const int* in_sizes, int n_in,
                              void* d_out, int out_size)
{
    const float* X    = (const float*)d_in[0];  // inputs_tensor [B,T,H]
    const float* S0   = (const float*)d_in[1];  // state_tensor  [1,B,H]
    const float* Wx   = (const float*)d_in[2];  // [H,H]
    const float* Wh   = (const float*)d_in[3];  // [H,H]
    const float* bias = (const float*)d_in[4];  // [H]
    float* out = (float*)d_out;                 // [T,B,H]

    (void)in_sizes; (void)n_in; (void)out_size;

    cudaFuncSetAttribute(rnn_steps,
                         cudaFuncAttributeMaxDynamicSharedMemorySize,
                         RNN_SMEM_BYTES);

    zero_cnt<<<32, 512>>>();

    dim3 g1(Hn / 64, (Bn * Tn) / 128);  // (8, 1024)
    gemm_xw<<<g1, 256>>>(X, Wx, bias, out);

    rnn_steps<<<128, 512, RNN_SMEM_BYTES>>>(S0, Wh, out);
}